// round 14
// baseline (speedup 1.0000x reference)
#include <cuda_runtime.h>
#include <cuda_bf16.h>
#include <cstdint>

// Problem constants
#define N_TOK   8192        // T*B = 512*16
#define C_DIM   512
#define R_DIM   64          // REDUCE
#define O_DIM   512         // OUT
#define NE      256         // 2^NBITS
#define ROW_LEN 32768       // OUT*REDUCE
#define Y_ELEMS (N_TOK * O_DIM)

// ---------------- device scratch (no allocation allowed) ----------------
__device__ float g_v[N_TOK * R_DIM];     // per-token reduced vector v (t-major)
__device__ int   g_q[N_TOK];             // per-token code qz1
__device__ int   g_hist[NE];             // zero-at-entry invariant (cleared by k_mid)
__device__ int   g_start[NE];
__device__ int   g_count[NE];
__device__ int   g_order[N_TOK];         // token ids grouped by code

// ---------------- f32x2 helpers (Blackwell packed fp32) ----------------
__device__ __forceinline__ void fma2(unsigned long long &d,
                                     unsigned long long a,
                                     unsigned long long b) {
    asm("fma.rn.f32x2 %0, %1, %2, %0;" : "+l"(d) : "l"(a), "l"(b));
}
__device__ __forceinline__ unsigned long long splat2(float f) {
    unsigned long long r;
    asm("mov.b64 %0, {%1, %1};" : "=l"(r) : "f"(f));
    return r;
}
__device__ __forceinline__ void unpack2(unsigned long long v, float &lo, float &hi) {
    asm("mov.b64 {%0, %1}, %2;" : "=f"(lo), "=f"(hi) : "l"(v));
}

// ---------------- kernel 1: front GEMM (v3) ----------------
// v[t,0..63] = pw_w1 @ x[t]; logits j -> sign bits -> g_q/g_hist.
// 24 warps (768 thr), K-split: half h = warp/12 covers k in [h*256, h*256+256),
// processed as 8 rounds of 32-k chunks. Within a half, warp w6 = warp%12 owns
// rows 6*w6..6*w6+5; lane owns tokens 2*lane, 2*lane+1 (of the block's 64).
// Both operands k-pair packed (even-k, odd-k interleaved float2) -> no splats:
// per k-pair: 1 LDS.128 (x: 2 tokens) + 3 LDS.128 (w: 6 rows) + 12 FFMA2.
// Tiles are register-prefetched one round ahead to overlap DRAM with compute.
#define XT_STRIDE 132       // words per kp row of X  (2*64 tok + 4 pad; 528B, 16B-aligned)
#define WT_STRIDE 148       // words per kp row of W  (2*72 rows + 4 pad; 592B, 16B-aligned)
#define XT_HALF   (16 * XT_STRIDE)   // 2112
#define WT_HALF   (16 * WT_STRIDE)   // 2368

__global__ void __launch_bounds__(768) k_front(
        const float* __restrict__ x,
        const float* __restrict__ map_w,
        const float* __restrict__ map_b,
        const float* __restrict__ pw_w1) {
    __shared__ __align__(16) float Xt[2 * XT_HALF];  // [h][kp][2t+bit]   16.9KB
    __shared__ __align__(16) float Wt[2 * WT_HALF];  // [h][kp][2r+bit]   18.9KB

    const int tid  = threadIdx.x;
    const int lane = tid & 31;
    const int warp = tid >> 5;           // 0..23
    const int h    = warp / 12;          // K half
    const int w6   = warp % 12;          // row group (6 rows)
    const int t0   = blockIdx.x * 64;

    unsigned long long acc[6][2];        // [row_local][token_local], k-pair packed
    #pragma unroll
    for (int i = 0; i < 6; i++) { acc[i][0] = 0ull; acc[i][1] = 0ull; }

    float xp[6], wp[6];

    // ---- prefetch helpers (inlined via lambdas) ----
    auto loadX = [&](int r) {
        #pragma unroll
        for (int i = 0; i < 6; i++) {
            int idx = tid + 768 * i;
            if (idx < 4096) {
                int hh = idx >> 11, rem = idx & 2047;
                int t = rem >> 5, k = rem & 31;
                xp[i] = x[(size_t)(t0 + t) * C_DIM + hh * 256 + r * 32 + k];
            }
        }
    };
    auto loadW = [&](int r) {
        #pragma unroll
        for (int i = 0; i < 6; i++) {
            int idx = tid + 768 * i;          // 0..4607, exact
            int hh = idx / 2304, rem = idx % 2304;
            int rr = rem >> 5, k = rem & 31;
            int col = hh * 256 + r * 32 + k;
            wp[i] = (rr < 64) ? pw_w1[rr * C_DIM + col]
                              : map_w[(rr - 64) * C_DIM + col];
        }
    };
    auto storeX = [&]() {
        #pragma unroll
        for (int i = 0; i < 6; i++) {
            int idx = tid + 768 * i;
            if (idx < 4096) {
                int hh = idx >> 11, rem = idx & 2047;
                int t = rem >> 5, k = rem & 31;
                // bank-conflict-free: stride 132 -> banks {2m, 2m+1} distinct
                Xt[hh * XT_HALF + (k >> 1) * XT_STRIDE + 2 * t + (k & 1)] = xp[i];
            }
        }
    };
    auto storeW = [&]() {
        #pragma unroll
        for (int i = 0; i < 6; i++) {
            int idx = tid + 768 * i;
            int hh = idx / 2304, rem = idx % 2304;
            int rr = rem >> 5, k = rem & 31;
            Wt[hh * WT_HALF + (k >> 1) * WT_STRIDE + 2 * rr + (k & 1)] = wp[i];
        }
    };

    loadX(0); loadW(0);

    const float* xb = Xt + h * XT_HALF + 4 * lane;
    const float* wb = Wt + h * WT_HALF + 12 * w6;

    for (int r = 0; r < 8; r++) {
        __syncthreads();                 // previous round's compute done
        storeX(); storeW();
        __syncthreads();
        if (r < 7) { loadX(r + 1); loadW(r + 1); }   // LDGs fly during compute

        #pragma unroll 8
        for (int kp = 0; kp < 16; kp++) {
            ulonglong2 vv = *(const ulonglong2*)(xb + kp * XT_STRIDE);
            #pragma unroll
            for (int rp = 0; rp < 3; rp++) {
                ulonglong2 ww = *(const ulonglong2*)(wb + kp * WT_STRIDE + 4 * rp);
                fma2(acc[2 * rp + 0][0], ww.x, vv.x);
                fma2(acc[2 * rp + 0][1], ww.x, vv.y);
                fma2(acc[2 * rp + 1][0], ww.y, vv.x);
                fma2(acc[2 * rp + 1][1], ww.y, vv.y);
            }
        }
    }

    // ---- epilogue: horizontal add (even+odd k), cross-half reduce in smem ----
    float y[6][2];
    #pragma unroll
    for (int rl = 0; rl < 6; rl++) {
        float lo, hi;
        unpack2(acc[rl][0], lo, hi); y[rl][0] = lo + hi;
        unpack2(acc[rl][1], lo, hi); y[rl][1] = lo + hi;
    }

    float* Vt = Wt;                      // reuse: Vt[t][r], stride 74 (64*74 = 4736 = 2*WT_HALF)
    __syncthreads();
    const int tA = 2 * lane, tB = 2 * lane + 1;
    if (h == 0) {
        #pragma unroll
        for (int rl = 0; rl < 6; rl++) {
            int rr = 6 * w6 + rl;
            Vt[tA * 74 + rr] = y[rl][0];
            Vt[tB * 74 + rr] = y[rl][1];
        }
    }
    __syncthreads();
    if (h == 1) {
        #pragma unroll
        for (int rl = 0; rl < 6; rl++) {
            int rr = 6 * w6 + rl;
            Vt[tA * 74 + rr] += y[rl][0];
            Vt[tB * 74 + rr] += y[rl][1];
        }
    }
    __syncthreads();

    // coalesced v write-out
    for (int idx = tid; idx < 64 * 64; idx += 768) {
        int t = idx >> 6, rr = idx & 63;
        g_v[(size_t)(t0 + t) * R_DIM + rr] = Vt[t * 74 + rr];
    }
    // code bits: one thread per token
    if (tid < 64) {
        int q = 0;
        #pragma unroll
        for (int j = 0; j < 8; j++) {
            if (Vt[tid * 74 + 64 + j] + map_b[j] > 0.f) q |= 1 << j;
        }
        g_q[t0 + tid] = q;
        atomicAdd(&g_hist[q], 1);
    }
}

// ---------------- kernel 2: fused scan + scatter + tail ----------------
__global__ void __launch_bounds__(1024) k_mid(float* __restrict__ out, int out_size) {
    __shared__ int cnt[NE];
    __shared__ int scn[NE];
    __shared__ int cur[NE];
    const int tid = threadIdx.x;

    if (tid < NE) {
        int hh = g_hist[tid];
        cnt[tid] = hh;
        scn[tid] = hh;
        g_hist[tid] = 0;        // restore zero-at-entry invariant for next replay
    }
    __syncthreads();
    #pragma unroll
    for (int off = 1; off < NE; off <<= 1) {
        int add = 0;
        if (tid < NE && tid >= off) add = scn[tid - off];
        __syncthreads();
        if (tid < NE) scn[tid] += add;
        __syncthreads();
    }
    if (tid < NE) {
        int excl = scn[tid] - cnt[tid];
        g_start[tid] = excl;
        g_count[tid] = cnt[tid];
        cur[tid]     = excl;
    }
    __syncthreads();

    #pragma unroll
    for (int i = 0; i < N_TOK / 1024; i++) {
        int t = tid + 1024 * i;
        int q = g_q[t];
        int pos = atomicAdd(&cur[q], 1);
        g_order[pos] = t;
    }

    for (int idx = Y_ELEMS + tid; idx < out_size; idx += 1024)
        out[idx] = 0.0f;
}

// ---------------- kernel 3: binned main GEMM ----------------
__global__ void __launch_bounds__(256) k_main(
        const float* __restrict__ w21,
        const float* __restrict__ w22,
        const float* __restrict__ bias,
        float* __restrict__ out) {
    __shared__ float Wsm[64 * 132];  // [r][o], stride 132 (16B-aligned float4)
    __shared__ float Vsm[64 * 36];   // [r][t], stride 36  (16B-aligned float4)

    const int c = blockIdx.x;
    const int n = g_count[c];
    if (n == 0) return;
    const int start = g_start[c];
    const int o0    = blockIdx.y * 128;
    const int tid   = threadIdx.x;

    {   // fused expert tile load: float4, 16 LDG.128/thread, deep MLP
        const float4* p1 = (const float4*)(w21 + (size_t)c * ROW_LEN + (size_t)o0 * R_DIM);
        const float4* p2 = (const float4*)(w22 + (size_t)(255 - c) * ROW_LEN + (size_t)o0 * R_DIM);
        #pragma unroll
        for (int i = 0; i < 8; i++) {
            int j  = tid + 256 * i;        // 0..2047 float4s
            int o  = j >> 4;               // 0..127
            int rb = (j & 15) * 4;         // r base
            float4 a = p1[j];
            float4 b = p2[j];
            Wsm[(rb + 0) * 132 + o] = a.x + b.x;
            Wsm[(rb + 1) * 132 + o] = a.y + b.y;
            Wsm[(rb + 2) * 132 + o] = a.z + b.z;
            Wsm[(rb + 3) * 132 + o] = a.w + b.w;
        }
    }

    const int ow = tid >> 3;      // 0..31 -> 4 outs each
    const int tg = tid & 7;       // 0..7  -> 4 tokens each
    const float b0 = bias[o0 + ow * 4 + 0];
    const float b1 = bias[o0 + ow * 4 + 1];
    const float b2 = bias[o0 + ow * 4 + 2];
    const float b3 = bias[o0 + ow * 4 + 3];

    for (int tb = 0; tb < n; tb += 32) {
        const int nt = min(32, n - tb);
        __syncthreads();
        {   // gather v: 16 threads/token, float4
            const int rq = tid & 15;
            for (int base = 0; base < nt; base += 16) {
                int t = base + (tid >> 4);
                if (t < nt) {
                    int tok = g_order[start + tb + t];
                    float4 v4 = *(const float4*)&g_v[(size_t)tok * R_DIM + rq * 4];
                    Vsm[(rq * 4 + 0) * 36 + t] = v4.x;
                    Vsm[(rq * 4 + 1) * 36 + t] = v4.y;
                    Vsm[(rq * 4 + 2) * 36 + t] = v4.z;
                    Vsm[(rq * 4 + 3) * 36 + t] = v4.w;
                }
            }
        }
        __syncthreads();

        unsigned long long acc[4][2];
        #pragma unroll
        for (int i = 0; i < 4; i++) { acc[i][0] = 0ull; acc[i][1] = 0ull; }

        #pragma unroll 8
        for (int r = 0; r < 64; r++) {
            float4 wv = *(const float4*)&Wsm[r * 132 + ow * 4];
            ulonglong2 vv = *(const ulonglong2*)&Vsm[r * 36 + tg * 4];
            unsigned long long w0 = splat2(wv.x);
            unsigned long long w1 = splat2(wv.y);
            unsigned long long w2s = splat2(wv.z);
            unsigned long long w3s = splat2(wv.w);
            fma2(acc[0][0], w0,  vv.x); fma2(acc[0][1], w0,  vv.y);
            fma2(acc[1][0], w1,  vv.x); fma2(acc[1][1], w1,  vv.y);
            fma2(acc[2][0], w2s, vv.x); fma2(acc[2][1], w2s, vv.y);
            fma2(acc[3][0], w3s, vv.x); fma2(acc[3][1], w3s, vv.y);
        }

        #pragma unroll
        for (int tp = 0; tp < 2; tp++) {
            float r0lo, r0hi, r1lo, r1hi, r2lo, r2hi, r3lo, r3hi;
            unpack2(acc[0][tp], r0lo, r0hi);
            unpack2(acc[1][tp], r1lo, r1hi);
            unpack2(acc[2][tp], r2lo, r2hi);
            unpack2(acc[3][tp], r3lo, r3hi);
            int tl = tb + tg * 4 + tp * 2;
            if (tl < n) {
                int tok = g_order[start + tl];
                float4 res = make_float4(r0lo + b0, r1lo + b1, r2lo + b2, r3lo + b3);
                *(float4*)&out[(size_t)tok * O_DIM + o0 + ow * 4] = res;
            }
            if (tl + 1 < n) {
                int tok = g_order[start + tl + 1];
                float4 res = make_float4(r0hi + b0, r1hi + b1, r2hi + b2, r3hi + b3);
                *(float4*)&out[(size_t)tok * O_DIM + o0 + ow * 4] = res;
            }
        }
    }
}

// ---------------- launch ----------------
extern "C" void kernel_launch(void* const* d_in, const int* in_sizes, int n_in,
                              void* d_out, int out_size) {
    const float* x      = (const float*)d_in[0];
    // d_in[1] = key, unused by the forward pass
    const float* map_w  = (const float*)d_in[2];
    const float* map_b  = (const float*)d_in[3];
    const float* pw_w1  = (const float*)d_in[4];
    const float* w21    = (const float*)d_in[5];
    const float* w22    = (const float*)d_in[6];
    const float* pw_B   = (const float*)d_in[7];
    float* out = (float*)d_out;

    k_front<<<N_TOK / 64, 768>>>(x, map_w, map_b, pw_w1);
    k_mid<<<1, 1024>>>(out, out_size);
    k_main<<<dim3(NE, O_DIM / 128), 256>>>(w21, w22, pw_B, out);
}

// round 15
// speedup vs baseline: 1.1012x; 1.1012x over previous
#include <cuda_runtime.h>
#include <cuda_bf16.h>
#include <cstdint>

// Problem constants
#define N_TOK   8192        // T*B = 512*16
#define C_DIM   512
#define R_DIM   64          // REDUCE
#define O_DIM   512         // OUT
#define NE      256         // 2^NBITS
#define ROW_LEN 32768       // OUT*REDUCE
#define Y_ELEMS (N_TOK * O_DIM)

// ---------------- device scratch (no allocation allowed) ----------------
__device__ float g_v[N_TOK * R_DIM];     // per-token reduced vector v (t-major)
__device__ int   g_q[N_TOK];             // per-token code qz1
__device__ int   g_hist[NE];             // zero-at-entry invariant (cleared by k_mid)
__device__ int   g_start[NE];
__device__ int   g_count[NE];
__device__ int   g_order[N_TOK];         // token ids grouped by code

// ---------------- f32x2 helpers (Blackwell packed fp32) ----------------
__device__ __forceinline__ void fma2(unsigned long long &d,
                                     unsigned long long a,
                                     unsigned long long b) {
    asm("fma.rn.f32x2 %0, %1, %2, %0;" : "+l"(d) : "l"(a), "l"(b));
}
__device__ __forceinline__ void unpack2(unsigned long long v, float &lo, float &hi) {
    asm("mov.b64 {%0, %1}, %2;" : "=f"(lo), "=f"(hi) : "l"(v));
}

// ---------------- kernel 1: front GEMM (unchanged from R13 win) ----------------
#define XT_STRIDE 132       // words per kp row of X  (2*64 tok + 4 pad)
#define WT_STRIDE 148       // words per kp row of W  (2*72 rows + 4 pad)
#define XT_HALF   (16 * XT_STRIDE)   // 2112
#define WT_HALF   (16 * WT_STRIDE)   // 2368

__global__ void __launch_bounds__(768) k_front(
        const float* __restrict__ x,
        const float* __restrict__ map_w,
        const float* __restrict__ map_b,
        const float* __restrict__ pw_w1) {
    __shared__ __align__(16) float Xt[2 * XT_HALF];
    __shared__ __align__(16) float Wt[2 * WT_HALF];

    const int tid  = threadIdx.x;
    const int lane = tid & 31;
    const int warp = tid >> 5;           // 0..23
    const int h    = warp / 12;          // K half
    const int w6   = warp % 12;          // row group (6 rows)
    const int t0   = blockIdx.x * 64;

    unsigned long long acc[6][2];
    #pragma unroll
    for (int i = 0; i < 6; i++) { acc[i][0] = 0ull; acc[i][1] = 0ull; }

    float xp[6], wp[6];

    auto loadX = [&](int r) {
        #pragma unroll
        for (int i = 0; i < 6; i++) {
            int idx = tid + 768 * i;
            if (idx < 4096) {
                int hh = idx >> 11, rem = idx & 2047;
                int t = rem >> 5, k = rem & 31;
                xp[i] = x[(size_t)(t0 + t) * C_DIM + hh * 256 + r * 32 + k];
            }
        }
    };
    auto loadW = [&](int r) {
        #pragma unroll
        for (int i = 0; i < 6; i++) {
            int idx = tid + 768 * i;
            int hh = idx / 2304, rem = idx % 2304;
            int rr = rem >> 5, k = rem & 31;
            int col = hh * 256 + r * 32 + k;
            wp[i] = (rr < 64) ? pw_w1[rr * C_DIM + col]
                              : map_w[(rr - 64) * C_DIM + col];
        }
    };
    auto storeX = [&]() {
        #pragma unroll
        for (int i = 0; i < 6; i++) {
            int idx = tid + 768 * i;
            if (idx < 4096) {
                int hh = idx >> 11, rem = idx & 2047;
                int t = rem >> 5, k = rem & 31;
                Xt[hh * XT_HALF + (k >> 1) * XT_STRIDE + 2 * t + (k & 1)] = xp[i];
            }
        }
    };
    auto storeW = [&]() {
        #pragma unroll
        for (int i = 0; i < 6; i++) {
            int idx = tid + 768 * i;
            int hh = idx / 2304, rem = idx % 2304;
            int rr = rem >> 5, k = rem & 31;
            Wt[hh * WT_HALF + (k >> 1) * WT_STRIDE + 2 * rr + (k & 1)] = wp[i];
        }
    };

    loadX(0); loadW(0);

    const float* xb = Xt + h * XT_HALF + 4 * lane;
    const float* wb = Wt + h * WT_HALF + 12 * w6;

    for (int r = 0; r < 8; r++) {
        __syncthreads();
        storeX(); storeW();
        __syncthreads();
        if (r < 7) { loadX(r + 1); loadW(r + 1); }

        #pragma unroll 8
        for (int kp = 0; kp < 16; kp++) {
            ulonglong2 vv = *(const ulonglong2*)(xb + kp * XT_STRIDE);
            #pragma unroll
            for (int rp = 0; rp < 3; rp++) {
                ulonglong2 ww = *(const ulonglong2*)(wb + kp * WT_STRIDE + 4 * rp);
                fma2(acc[2 * rp + 0][0], ww.x, vv.x);
                fma2(acc[2 * rp + 0][1], ww.x, vv.y);
                fma2(acc[2 * rp + 1][0], ww.y, vv.x);
                fma2(acc[2 * rp + 1][1], ww.y, vv.y);
            }
        }
    }

    float y[6][2];
    #pragma unroll
    for (int rl = 0; rl < 6; rl++) {
        float lo, hi;
        unpack2(acc[rl][0], lo, hi); y[rl][0] = lo + hi;
        unpack2(acc[rl][1], lo, hi); y[rl][1] = lo + hi;
    }

    float* Vt = Wt;                      // reuse: Vt[t][r], stride 74
    __syncthreads();
    const int tA = 2 * lane, tB = 2 * lane + 1;
    if (h == 0) {
        #pragma unroll
        for (int rl = 0; rl < 6; rl++) {
            int rr = 6 * w6 + rl;
            Vt[tA * 74 + rr] = y[rl][0];
            Vt[tB * 74 + rr] = y[rl][1];
        }
    }
    __syncthreads();
    if (h == 1) {
        #pragma unroll
        for (int rl = 0; rl < 6; rl++) {
            int rr = 6 * w6 + rl;
            Vt[tA * 74 + rr] += y[rl][0];
            Vt[tB * 74 + rr] += y[rl][1];
        }
    }
    __syncthreads();

    for (int idx = tid; idx < 64 * 64; idx += 768) {
        int t = idx >> 6, rr = idx & 63;
        g_v[(size_t)(t0 + t) * R_DIM + rr] = Vt[t * 74 + rr];
    }
    if (tid < 64) {
        int q = 0;
        #pragma unroll
        for (int j = 0; j < 8; j++) {
            if (Vt[tid * 74 + 64 + j] + map_b[j] > 0.f) q |= 1 << j;
        }
        g_q[t0 + tid] = q;
        atomicAdd(&g_hist[q], 1);
    }
}

// ---------------- kernel 2: fused scan + scatter + tail ----------------
__global__ void __launch_bounds__(1024) k_mid(float* __restrict__ out, int out_size) {
    __shared__ int cnt[NE];
    __shared__ int scn[NE];
    __shared__ int cur[NE];
    const int tid = threadIdx.x;

    if (tid < NE) {
        int hh = g_hist[tid];
        cnt[tid] = hh;
        scn[tid] = hh;
        g_hist[tid] = 0;        // restore zero-at-entry invariant for next replay
    }
    __syncthreads();
    #pragma unroll
    for (int off = 1; off < NE; off <<= 1) {
        int add = 0;
        if (tid < NE && tid >= off) add = scn[tid - off];
        __syncthreads();
        if (tid < NE) scn[tid] += add;
        __syncthreads();
    }
    if (tid < NE) {
        int excl = scn[tid] - cnt[tid];
        g_start[tid] = excl;
        g_count[tid] = cnt[tid];
        cur[tid]     = excl;
    }
    __syncthreads();

    #pragma unroll
    for (int i = 0; i < N_TOK / 1024; i++) {
        int t = tid + 1024 * i;
        int q = g_q[t];
        int pos = atomicAdd(&cur[q], 1);
        g_order[pos] = t;
    }

    for (int idx = Y_ELEMS + tid; idx < out_size; idx += 1024)
        out[idx] = 0.0f;
}

// ---------------- kernel 3: binned main GEMM (v2: conflict-free layouts) ----------------
// block (c, oy): Wsm[o][r] = w21[c] + w22[255-c] for outs [o0, o0+128), then per
// 32-token chunk of bin c: y[tok,o] = dot(Wsm[o,:], Vsm[tok,:]) + bias[o].
// Stride 76 (== 12 mod 32):
//   STS: both tiles stored as contiguous STS.128 -> conflict-free.
//   LDS W: warp lanes step o by 1 -> bank-quad offsets {0,12,24,4} -> conflict-free.
//   LDS V: warp lanes step tok by 1 -> offsets {0,12,24,4,16,28,8,20} -> conflict-free.
// Thread owns outs {ow + 32*ol} and tokens {tg + 8*tl}; accumulation is r-pair
// packed f32x2 on BOTH operands (no splats), horizontal add at the end.
#define WS 76
__global__ void __launch_bounds__(256) k_main(
        const float* __restrict__ w21,
        const float* __restrict__ w22,
        const float* __restrict__ bias,
        float* __restrict__ out) {
    __shared__ __align__(16) float Wsm[128 * WS];  // [o][r]  38.9KB
    __shared__ __align__(16) float Vsm[32 * WS];   // [t][r]   9.7KB

    const int c = blockIdx.x;
    const int n = g_count[c];
    if (n == 0) return;
    const int start = g_start[c];
    const int o0    = blockIdx.y * 128;
    const int tid   = threadIdx.x;

    {   // fused expert tile: 16 LDG.128/thread (front-batched), contiguous STS.128
        const float4* p1 = (const float4*)(w21 + (size_t)c * ROW_LEN + (size_t)o0 * R_DIM);
        const float4* p2 = (const float4*)(w22 + (size_t)(255 - c) * ROW_LEN + (size_t)o0 * R_DIM);
        #pragma unroll
        for (int i = 0; i < 8; i++) {
            int j  = tid + 256 * i;        // 0..2047 float4s, o-major (r contiguous)
            int o  = j >> 4;               // 0..127
            int rb = j & 15;               // float4 index within row
            float4 a = p1[j];
            float4 b = p2[j];
            float4 s = make_float4(a.x + b.x, a.y + b.y, a.z + b.z, a.w + b.w);
            *(float4*)&Wsm[o * WS + rb * 4] = s;
        }
    }

    const int ow = tid >> 3;      // 0..31; outs = ow + 32*ol
    const int tg = tid & 7;       // 0..7;  toks = tg + 8*tl
    float bia[4];
    #pragma unroll
    for (int ol = 0; ol < 4; ol++) bia[ol] = bias[o0 + ow + 32 * ol];

    for (int tb = 0; tb < n; tb += 32) {
        const int nt = min(32, n - tb);
        __syncthreads();
        {   // gather v: 16 threads/token, contiguous STS.128
            const int rq = tid & 15;
            for (int base = 0; base < nt; base += 16) {
                int t = base + (tid >> 4);
                if (t < nt) {
                    int tok = g_order[start + tb + t];
                    float4 v4 = *(const float4*)&g_v[(size_t)tok * R_DIM + rq * 4];
                    *(float4*)&Vsm[t * WS + rq * 4] = v4;
                }
            }
        }
        __syncthreads();

        unsigned long long acc[4][4];   // [ol][tl], r-pair packed partial dots
        #pragma unroll
        for (int i = 0; i < 4; i++)
            #pragma unroll
            for (int j = 0; j < 4; j++) acc[i][j] = 0ull;

        #pragma unroll 4
        for (int rb = 0; rb < 16; rb++) {
            ulonglong2 w2[4], v2[4];
            #pragma unroll
            for (int ol = 0; ol < 4; ol++)
                w2[ol] = *(const ulonglong2*)&Wsm[(ow + 32 * ol) * WS + rb * 4];
            #pragma unroll
            for (int tl = 0; tl < 4; tl++)
                v2[tl] = *(const ulonglong2*)&Vsm[(tg + 8 * tl) * WS + rb * 4];
            #pragma unroll
            for (int ol = 0; ol < 4; ol++)
                #pragma unroll
                for (int tl = 0; tl < 4; tl++) {
                    fma2(acc[ol][tl], w2[ol].x, v2[tl].x);
                    fma2(acc[ol][tl], w2[ol].y, v2[tl].y);
                }
        }

        #pragma unroll
        for (int tl = 0; tl < 4; tl++) {
            int t = tg + 8 * tl;
            if (tb + t < n) {
                int tok = g_order[start + tb + t];
                #pragma unroll
                for (int ol = 0; ol < 4; ol++) {
                    float lo, hi;
                    unpack2(acc[ol][tl], lo, hi);
                    out[(size_t)tok * O_DIM + o0 + ow + 32 * ol] = lo + hi + bia[ol];
                }
            }
        }
    }
}

// ---------------- launch ----------------
extern "C" void kernel_launch(void* const* d_in, const int* in_sizes, int n_in,
                              void* d_out, int out_size) {
    const float* x      = (const float*)d_in[0];
    // d_in[1] = key, unused by the forward pass
    const float* map_w  = (const float*)d_in[2];
    const float* map_b  = (const float*)d_in[3];
    const float* pw_w1  = (const float*)d_in[4];
    const float* w21    = (const float*)d_in[5];
    const float* w22    = (const float*)d_in[6];
    const float* pw_B   = (const float*)d_in[7];
    float* out = (float*)d_out;

    k_front<<<N_TOK / 64, 768>>>(x, map_w, map_b, pw_w1);
    k_mid<<<1, 1024>>>(out, out_size);
    k_main<<<dim3(NE, O_DIM / 128), 256>>>(w21, w22, pw_B, out);
}

// round 16
// speedup vs baseline: 1.1166x; 1.0141x over previous
#include <cuda_runtime.h>
#include <cuda_bf16.h>
#include <cstdint>

// Problem constants
#define N_TOK   8192        // T*B = 512*16
#define C_DIM   512
#define R_DIM   64          // REDUCE
#define O_DIM   512         // OUT
#define NE      256         // 2^NBITS
#define ROW_LEN 32768       // OUT*REDUCE
#define Y_ELEMS (N_TOK * O_DIM)
#define MAX_WORK 1024       // >= 256 + 8192/32 = 512

// ---------------- device scratch (no allocation allowed) ----------------
__device__ float g_v[N_TOK * R_DIM];     // per-token reduced vector v (t-major)
__device__ int   g_q[N_TOK];             // per-token code qz1
__device__ int   g_hist[NE];             // zero-at-entry invariant (cleared by k_mid)
__device__ int   g_start[NE];
__device__ int   g_count[NE];
__device__ int   g_order[N_TOK];         // token ids grouped by code
__device__ int   g_work[MAX_WORK];       // (code << 16) | chunk_tb
__device__ int   g_nwork;

// ---------------- f32x2 helpers (Blackwell packed fp32) ----------------
__device__ __forceinline__ void fma2(unsigned long long &d,
                                     unsigned long long a,
                                     unsigned long long b) {
    asm("fma.rn.f32x2 %0, %1, %2, %0;" : "+l"(d) : "l"(a), "l"(b));
}
__device__ __forceinline__ void unpack2(unsigned long long v, float &lo, float &hi) {
    asm("mov.b64 {%0, %1}, %2;" : "=f"(lo), "=f"(hi) : "l"(v));
}

// ---------------- kernel 1: front GEMM ----------------
#define XT_STRIDE 132       // words per kp row of X  (2*64 tok + 4 pad)
#define WT_STRIDE 148       // words per kp row of W  (2*72 rows + 4 pad)
#define XT_HALF   (16 * XT_STRIDE)   // 2112
#define WT_HALF   (16 * WT_STRIDE)   // 2368

__global__ void __launch_bounds__(768) k_front(
        const float* __restrict__ x,
        const float* __restrict__ map_w,
        const float* __restrict__ map_b,
        const float* __restrict__ pw_w1) {
    __shared__ __align__(16) float Xt[2 * XT_HALF];
    __shared__ __align__(16) float Wt[2 * WT_HALF];

    const int tid  = threadIdx.x;
    const int lane = tid & 31;
    const int warp = tid >> 5;           // 0..23
    const int h    = warp / 12;          // K half
    const int w6   = warp % 12;          // row group (6 rows)
    const int t0   = blockIdx.x * 64;

    unsigned long long acc[6][2];
    #pragma unroll
    for (int i = 0; i < 6; i++) { acc[i][0] = 0ull; acc[i][1] = 0ull; }

    float xp[6], wp[6];

    // idx = tid + 768*i; X spans 4096 entries (i<5 full, i=5 needs tid<256).
    // W spans 4608 exactly; half boundary 2304 => hh = (i>=3), constant per i.
    auto loadX = [&](int r) {
        #pragma unroll
        for (int i = 0; i < 6; i++) {
            if (i < 5 || tid < 256) {
                int idx = tid + 768 * i;
                int hh = idx >> 11, rem = idx & 2047;
                int t = rem >> 5, k = rem & 31;
                xp[i] = x[(size_t)(t0 + t) * C_DIM + hh * 256 + r * 32 + k];
            }
        }
    };
    auto loadW = [&](int r) {
        #pragma unroll
        for (int i = 0; i < 6; i++) {
            const int hh  = (i >= 3) ? 1 : 0;
            int rem = tid + 768 * i - 2304 * hh;     // 0..2303
            int rr = rem >> 5, k = rem & 31;
            int col = hh * 256 + r * 32 + k;
            wp[i] = (rr < 64) ? pw_w1[rr * C_DIM + col]
                              : map_w[(rr - 64) * C_DIM + col];
        }
    };
    auto storeX = [&]() {
        #pragma unroll
        for (int i = 0; i < 6; i++) {
            if (i < 5 || tid < 256) {
                int idx = tid + 768 * i;
                int hh = idx >> 11, rem = idx & 2047;
                int t = rem >> 5, k = rem & 31;
                Xt[hh * XT_HALF + (k >> 1) * XT_STRIDE + 2 * t + (k & 1)] = xp[i];
            }
        }
    };
    auto storeW = [&]() {
        #pragma unroll
        for (int i = 0; i < 6; i++) {
            const int hh  = (i >= 3) ? 1 : 0;
            int rem = tid + 768 * i - 2304 * hh;
            int rr = rem >> 5, k = rem & 31;
            Wt[hh * WT_HALF + (k >> 1) * WT_STRIDE + 2 * rr + (k & 1)] = wp[i];
        }
    };

    loadX(0); loadW(0);

    const float* xb = Xt + h * XT_HALF + 4 * lane;
    const float* wb = Wt + h * WT_HALF + 12 * w6;

    for (int r = 0; r < 8; r++) {
        __syncthreads();
        storeX(); storeW();
        __syncthreads();
        if (r < 7) { loadX(r + 1); loadW(r + 1); }

        #pragma unroll 8
        for (int kp = 0; kp < 16; kp++) {
            ulonglong2 vv = *(const ulonglong2*)(xb + kp * XT_STRIDE);
            #pragma unroll
            for (int rp = 0; rp < 3; rp++) {
                ulonglong2 ww = *(const ulonglong2*)(wb + kp * WT_STRIDE + 4 * rp);
                fma2(acc[2 * rp + 0][0], ww.x, vv.x);
                fma2(acc[2 * rp + 0][1], ww.x, vv.y);
                fma2(acc[2 * rp + 1][0], ww.y, vv.x);
                fma2(acc[2 * rp + 1][1], ww.y, vv.y);
            }
        }
    }

    float y[6][2];
    #pragma unroll
    for (int rl = 0; rl < 6; rl++) {
        float lo, hi;
        unpack2(acc[rl][0], lo, hi); y[rl][0] = lo + hi;
        unpack2(acc[rl][1], lo, hi); y[rl][1] = lo + hi;
    }

    float* Vt = Wt;                      // reuse: Vt[t][r], stride 74
    __syncthreads();
    const int tA = 2 * lane, tB = 2 * lane + 1;
    if (h == 0) {
        #pragma unroll
        for (int rl = 0; rl < 6; rl++) {
            int rr = 6 * w6 + rl;
            Vt[tA * 74 + rr] = y[rl][0];
            Vt[tB * 74 + rr] = y[rl][1];
        }
    }
    __syncthreads();
    if (h == 1) {
        #pragma unroll
        for (int rl = 0; rl < 6; rl++) {
            int rr = 6 * w6 + rl;
            Vt[tA * 74 + rr] += y[rl][0];
            Vt[tB * 74 + rr] += y[rl][1];
        }
    }
    __syncthreads();

    for (int idx = tid; idx < 64 * 64; idx += 768) {
        int t = idx >> 6, rr = idx & 63;
        g_v[(size_t)(t0 + t) * R_DIM + rr] = Vt[t * 74 + rr];
    }
    if (tid < 64) {
        int q = 0;
        #pragma unroll
        for (int j = 0; j < 8; j++) {
            if (Vt[tid * 74 + 64 + j] + map_b[j] > 0.f) q |= 1 << j;
        }
        g_q[t0 + tid] = q;
        atomicAdd(&g_hist[q], 1);
    }
}

// ---------------- kernel 2: scan + scatter + work list + tail ----------------
__global__ void __launch_bounds__(1024) k_mid(float* __restrict__ out, int out_size) {
    __shared__ int cnt[NE];
    __shared__ int scn[NE];
    __shared__ int cur[NE];
    __shared__ int wcur;
    const int tid = threadIdx.x;

    if (tid == 0) wcur = 0;
    if (tid < NE) {
        int hh = g_hist[tid];
        cnt[tid] = hh;
        scn[tid] = hh;
        g_hist[tid] = 0;        // restore zero-at-entry invariant for next replay
    }
    __syncthreads();
    #pragma unroll
    for (int off = 1; off < NE; off <<= 1) {
        int add = 0;
        if (tid < NE && tid >= off) add = scn[tid - off];
        __syncthreads();
        if (tid < NE) scn[tid] += add;
        __syncthreads();
    }
    if (tid < NE) {
        int excl = scn[tid] - cnt[tid];
        g_start[tid] = excl;
        g_count[tid] = cnt[tid];
        cur[tid]     = excl;
        // emit one work item per 32-token chunk of this bin
        int nch = (cnt[tid] + 31) >> 5;
        if (nch > 0) {
            int pos = atomicAdd(&wcur, nch);
            for (int i = 0; i < nch; i++)
                g_work[pos + i] = (tid << 16) | (i << 5);
        }
    }
    __syncthreads();
    if (tid == 0) g_nwork = wcur;

    #pragma unroll
    for (int i = 0; i < N_TOK / 1024; i++) {
        int t = tid + 1024 * i;
        int q = g_q[t];
        int pos = atomicAdd(&cur[q], 1);
        g_order[pos] = t;
    }

    for (int idx = Y_ELEMS + tid; idx < out_size; idx += 1024)
        out[idx] = 0.0f;
}

// ---------------- kernel 3: binned main GEMM (v3: chunk-balanced) ----------------
// block (w, oy): work item w = (code c, chunk tb). Exactly ONE 32-token chunk
// per block -> no straggler bins. Wsm[o][r] stride 76 (==12 mod 32): all STS
// contiguous .128, all LDS conflict-free (see R14 bank math).
#define WS 76
__global__ void __launch_bounds__(256) k_main(
        const float* __restrict__ w21,
        const float* __restrict__ w22,
        const float* __restrict__ bias,
        float* __restrict__ out) {
    __shared__ __align__(16) float Wsm[128 * WS];  // [o][r]  38.9KB
    __shared__ __align__(16) float Vsm[32 * WS];   // [t][r]   9.7KB

    const int w = blockIdx.x;
    if (w >= g_nwork) return;
    const int e  = g_work[w];
    const int c  = e >> 16;
    const int tb = e & 0xffff;
    const int nt = min(32, g_count[c] - tb);
    const int start = g_start[c] + tb;
    const int o0    = blockIdx.y * 128;
    const int tid   = threadIdx.x;

    // ---- single load phase: W tile + V gather, one sync ----
    {   // fused expert tile: 16 LDG.128/thread (front-batched), contiguous STS.128
        const float4* p1 = (const float4*)(w21 + (size_t)c * ROW_LEN + (size_t)o0 * R_DIM);
        const float4* p2 = (const float4*)(w22 + (size_t)(255 - c) * ROW_LEN + (size_t)o0 * R_DIM);
        #pragma unroll
        for (int i = 0; i < 8; i++) {
            int j  = tid + 256 * i;        // 0..2047 float4s, o-major (r contiguous)
            int o  = j >> 4;
            int rb = j & 15;
            float4 a = p1[j];
            float4 b = p2[j];
            *(float4*)&Wsm[o * WS + rb * 4] =
                make_float4(a.x + b.x, a.y + b.y, a.z + b.z, a.w + b.w);
        }
    }
    {   // gather v: 16 threads/token, contiguous STS.128
        const int rq = tid & 15;
        #pragma unroll
        for (int base = 0; base < 32; base += 16) {
            int t = base + (tid >> 4);
            if (t < nt) {
                int tok = g_order[start + t];
                float4 v4 = *(const float4*)&g_v[(size_t)tok * R_DIM + rq * 4];
                *(float4*)&Vsm[t * WS + rq * 4] = v4;
            }
        }
    }

    const int ow = tid >> 3;      // 0..31; outs = ow + 32*ol
    const int tg = tid & 7;       // 0..7;  toks = tg + 8*tl
    float bia[4];
    #pragma unroll
    for (int ol = 0; ol < 4; ol++) bia[ol] = bias[o0 + ow + 32 * ol];

    __syncthreads();

    unsigned long long acc[4][4];   // [ol][tl], r-pair packed partial dots
    #pragma unroll
    for (int i = 0; i < 4; i++)
        #pragma unroll
        for (int j = 0; j < 4; j++) acc[i][j] = 0ull;

    #pragma unroll 4
    for (int rb = 0; rb < 16; rb++) {
        ulonglong2 w2[4], v2[4];
        #pragma unroll
        for (int ol = 0; ol < 4; ol++)
            w2[ol] = *(const ulonglong2*)&Wsm[(ow + 32 * ol) * WS + rb * 4];
        #pragma unroll
        for (int tl = 0; tl < 4; tl++)
            v2[tl] = *(const ulonglong2*)&Vsm[(tg + 8 * tl) * WS + rb * 4];
        #pragma unroll
        for (int ol = 0; ol < 4; ol++)
            #pragma unroll
            for (int tl = 0; tl < 4; tl++) {
                fma2(acc[ol][tl], w2[ol].x, v2[tl].x);
                fma2(acc[ol][tl], w2[ol].y, v2[tl].y);
            }
    }

    #pragma unroll
    for (int tl = 0; tl < 4; tl++) {
        int t = tg + 8 * tl;
        if (t < nt) {
            int tok = g_order[start + t];
            #pragma unroll
            for (int ol = 0; ol < 4; ol++) {
                float lo, hi;
                unpack2(acc[ol][tl], lo, hi);
                out[(size_t)tok * O_DIM + o0 + ow + 32 * ol] = lo + hi + bia[ol];
            }
        }
    }
}

// ---------------- launch ----------------
extern "C" void kernel_launch(void* const* d_in, const int* in_sizes, int n_in,
                              void* d_out, int out_size) {
    const float* x      = (const float*)d_in[0];
    // d_in[1] = key, unused by the forward pass
    const float* map_w  = (const float*)d_in[2];
    const float* map_b  = (const float*)d_in[3];
    const float* pw_w1  = (const float*)d_in[4];
    const float* w21    = (const float*)d_in[5];
    const float* w22    = (const float*)d_in[6];
    const float* pw_B   = (const float*)d_in[7];
    float* out = (float*)d_out;

    k_front<<<N_TOK / 64, 768>>>(x, map_w, map_b, pw_w1);
    k_mid<<<1, 1024>>>(out, out_size);
    // upper bound on chunks: 256 + 8192/32 = 512
    k_main<<<dim3(512, O_DIM / 128), 256>>>(w21, w22, pw_B, out);
}

// round 17
// speedup vs baseline: 1.1578x; 1.0369x over previous
#include <cuda_runtime.h>
#include <cuda_bf16.h>
#include <cstdint>

// Problem constants
#define N_TOK   8192        // T*B = 512*16
#define C_DIM   512
#define R_DIM   64          // REDUCE
#define O_DIM   512         // OUT
#define NE      256         // 2^NBITS
#define ROW_LEN 32768       // OUT*REDUCE
#define Y_ELEMS (N_TOK * O_DIM)
#define MAX_WORK 1024       // >= 256 + 8192/32 = 512

// ---------------- device scratch (no allocation allowed) ----------------
__device__ float g_v[N_TOK * R_DIM];     // per-token reduced vector v (t-major)
__device__ int   g_q[N_TOK];             // per-token code qz1
__device__ int   g_hist[NE];             // zero-at-entry invariant (cleared by k_mid)
__device__ int   g_start[NE];
__device__ int   g_count[NE];
__device__ int   g_cursor[NE];           // scatter cursors (init by k_mid each call)
__device__ int   g_order[N_TOK];         // token ids grouped by code
__device__ int   g_work[MAX_WORK];       // (code << 16) | chunk_tb
__device__ int   g_nwork;

// ---------------- f32x2 helpers (Blackwell packed fp32) ----------------
__device__ __forceinline__ void fma2(unsigned long long &d,
                                     unsigned long long a,
                                     unsigned long long b) {
    asm("fma.rn.f32x2 %0, %1, %2, %0;" : "+l"(d) : "l"(a), "l"(b));
}
__device__ __forceinline__ void unpack2(unsigned long long v, float &lo, float &hi) {
    asm("mov.b64 {%0, %1}, %2;" : "=f"(lo), "=f"(hi) : "l"(v));
}

// ---------------- kernel 1: front GEMM (unchanged) ----------------
#define XT_STRIDE 132       // words per kp row of X  (2*64 tok + 4 pad)
#define WT_STRIDE 148       // words per kp row of W  (2*72 rows + 4 pad)
#define XT_HALF   (16 * XT_STRIDE)   // 2112
#define WT_HALF   (16 * WT_STRIDE)   // 2368

__global__ void __launch_bounds__(768) k_front(
        const float* __restrict__ x,
        const float* __restrict__ map_w,
        const float* __restrict__ map_b,
        const float* __restrict__ pw_w1) {
    __shared__ __align__(16) float Xt[2 * XT_HALF];
    __shared__ __align__(16) float Wt[2 * WT_HALF];

    const int tid  = threadIdx.x;
    const int lane = tid & 31;
    const int warp = tid >> 5;           // 0..23
    const int h    = warp / 12;          // K half
    const int w6   = warp % 12;          // row group (6 rows)
    const int t0   = blockIdx.x * 64;

    unsigned long long acc[6][2];
    #pragma unroll
    for (int i = 0; i < 6; i++) { acc[i][0] = 0ull; acc[i][1] = 0ull; }

    float xp[6], wp[6];

    auto loadX = [&](int r) {
        #pragma unroll
        for (int i = 0; i < 6; i++) {
            if (i < 5 || tid < 256) {
                int idx = tid + 768 * i;
                int hh = idx >> 11, rem = idx & 2047;
                int t = rem >> 5, k = rem & 31;
                xp[i] = x[(size_t)(t0 + t) * C_DIM + hh * 256 + r * 32 + k];
            }
        }
    };
    auto loadW = [&](int r) {
        #pragma unroll
        for (int i = 0; i < 6; i++) {
            const int hh  = (i >= 3) ? 1 : 0;
            int rem = tid + 768 * i - 2304 * hh;     // 0..2303
            int rr = rem >> 5, k = rem & 31;
            int col = hh * 256 + r * 32 + k;
            wp[i] = (rr < 64) ? pw_w1[rr * C_DIM + col]
                              : map_w[(rr - 64) * C_DIM + col];
        }
    };
    auto storeX = [&]() {
        #pragma unroll
        for (int i = 0; i < 6; i++) {
            if (i < 5 || tid < 256) {
                int idx = tid + 768 * i;
                int hh = idx >> 11, rem = idx & 2047;
                int t = rem >> 5, k = rem & 31;
                Xt[hh * XT_HALF + (k >> 1) * XT_STRIDE + 2 * t + (k & 1)] = xp[i];
            }
        }
    };
    auto storeW = [&]() {
        #pragma unroll
        for (int i = 0; i < 6; i++) {
            const int hh  = (i >= 3) ? 1 : 0;
            int rem = tid + 768 * i - 2304 * hh;
            int rr = rem >> 5, k = rem & 31;
            Wt[hh * WT_HALF + (k >> 1) * WT_STRIDE + 2 * rr + (k & 1)] = wp[i];
        }
    };

    loadX(0); loadW(0);

    const float* xb = Xt + h * XT_HALF + 4 * lane;
    const float* wb = Wt + h * WT_HALF + 12 * w6;

    for (int r = 0; r < 8; r++) {
        __syncthreads();
        storeX(); storeW();
        __syncthreads();
        if (r < 7) { loadX(r + 1); loadW(r + 1); }

        #pragma unroll 8
        for (int kp = 0; kp < 16; kp++) {
            ulonglong2 vv = *(const ulonglong2*)(xb + kp * XT_STRIDE);
            #pragma unroll
            for (int rp = 0; rp < 3; rp++) {
                ulonglong2 ww = *(const ulonglong2*)(wb + kp * WT_STRIDE + 4 * rp);
                fma2(acc[2 * rp + 0][0], ww.x, vv.x);
                fma2(acc[2 * rp + 0][1], ww.x, vv.y);
                fma2(acc[2 * rp + 1][0], ww.y, vv.x);
                fma2(acc[2 * rp + 1][1], ww.y, vv.y);
            }
        }
    }

    float y[6][2];
    #pragma unroll
    for (int rl = 0; rl < 6; rl++) {
        float lo, hi;
        unpack2(acc[rl][0], lo, hi); y[rl][0] = lo + hi;
        unpack2(acc[rl][1], lo, hi); y[rl][1] = lo + hi;
    }

    float* Vt = Wt;                      // reuse: Vt[t][r], stride 74
    __syncthreads();
    const int tA = 2 * lane, tB = 2 * lane + 1;
    if (h == 0) {
        #pragma unroll
        for (int rl = 0; rl < 6; rl++) {
            int rr = 6 * w6 + rl;
            Vt[tA * 74 + rr] = y[rl][0];
            Vt[tB * 74 + rr] = y[rl][1];
        }
    }
    __syncthreads();
    if (h == 1) {
        #pragma unroll
        for (int rl = 0; rl < 6; rl++) {
            int rr = 6 * w6 + rl;
            Vt[tA * 74 + rr] += y[rl][0];
            Vt[tB * 74 + rr] += y[rl][1];
        }
    }
    __syncthreads();

    for (int idx = tid; idx < 64 * 64; idx += 768) {
        int t = idx >> 6, rr = idx & 63;
        g_v[(size_t)(t0 + t) * R_DIM + rr] = Vt[t * 74 + rr];
    }
    if (tid < 64) {
        int q = 0;
        #pragma unroll
        for (int j = 0; j < 8; j++) {
            if (Vt[tid * 74 + 64 + j] + map_b[j] > 0.f) q |= 1 << j;
        }
        g_q[t0 + tid] = q;
        atomicAdd(&g_hist[q], 1);
    }
}

// ---------------- kernel 2: scan + work list + tail (NO scatter) ----------------
__global__ void __launch_bounds__(256) k_mid(float* __restrict__ out, int out_size) {
    __shared__ int cnt[NE];
    __shared__ int scn[NE];
    __shared__ int wcur;
    const int tid = threadIdx.x;

    if (tid == 0) wcur = 0;
    {
        int hh = g_hist[tid];
        cnt[tid] = hh;
        scn[tid] = hh;
        g_hist[tid] = 0;        // restore zero-at-entry invariant for next replay
    }
    __syncthreads();
    #pragma unroll
    for (int off = 1; off < NE; off <<= 1) {
        int add = (tid >= off) ? scn[tid - off] : 0;
        __syncthreads();
        scn[tid] += add;
        __syncthreads();
    }
    {
        int excl = scn[tid] - cnt[tid];
        g_start[tid]  = excl;
        g_count[tid]  = cnt[tid];
        g_cursor[tid] = excl;   // parallel scatter cursors
        int nch = (cnt[tid] + 31) >> 5;
        if (nch > 0) {
            int pos = atomicAdd(&wcur, nch);
            for (int i = 0; i < nch; i++)
                g_work[pos + i] = (tid << 16) | (i << 5);
        }
    }
    __syncthreads();
    if (tid == 0) g_nwork = wcur;

    // loss + any tail padding
    for (int idx = Y_ELEMS + tid; idx < out_size; idx += 256)
        out[idx] = 0.0f;
}

// ---------------- kernel 2b: parallel scatter (global atomics) ----------------
// 8192 threads across 64 blocks: per-address L2-atomic chains (~32 ops x ~30cyc)
// run in parallel across 256 cursor addresses / LTS slices, instead of
// serializing through one SM's shared-memory atomic unit.
__global__ void __launch_bounds__(128) k_scatter() {
    int t = blockIdx.x * 128 + threadIdx.x;
    int q = g_q[t];
    int pos = atomicAdd(&g_cursor[q], 1);
    g_order[pos] = t;
}

// ---------------- kernel 3: binned main GEMM (unchanged from R15) ----------------
#define WS 76
__global__ void __launch_bounds__(256) k_main(
        const float* __restrict__ w21,
        const float* __restrict__ w22,
        const float* __restrict__ bias,
        float* __restrict__ out) {
    __shared__ __align__(16) float Wsm[128 * WS];  // [o][r]  38.9KB
    __shared__ __align__(16) float Vsm[32 * WS];   // [t][r]   9.7KB

    const int w = blockIdx.x;
    if (w >= g_nwork) return;
    const int e  = g_work[w];
    const int c  = e >> 16;
    const int tb = e & 0xffff;
    const int nt = min(32, g_count[c] - tb);
    const int start = g_start[c] + tb;
    const int o0    = blockIdx.y * 128;
    const int tid   = threadIdx.x;

    {   // fused expert tile: 16 LDG.128/thread (front-batched), contiguous STS.128
        const float4* p1 = (const float4*)(w21 + (size_t)c * ROW_LEN + (size_t)o0 * R_DIM);
        const float4* p2 = (const float4*)(w22 + (size_t)(255 - c) * ROW_LEN + (size_t)o0 * R_DIM);
        #pragma unroll
        for (int i = 0; i < 8; i++) {
            int j  = tid + 256 * i;        // 0..2047 float4s, o-major (r contiguous)
            int o  = j >> 4;
            int rb = j & 15;
            float4 a = p1[j];
            float4 b = p2[j];
            *(float4*)&Wsm[o * WS + rb * 4] =
                make_float4(a.x + b.x, a.y + b.y, a.z + b.z, a.w + b.w);
        }
    }
    {   // gather v: 16 threads/token, contiguous STS.128
        const int rq = tid & 15;
        #pragma unroll
        for (int base = 0; base < 32; base += 16) {
            int t = base + (tid >> 4);
            if (t < nt) {
                int tok = g_order[start + t];
                float4 v4 = *(const float4*)&g_v[(size_t)tok * R_DIM + rq * 4];
                *(float4*)&Vsm[t * WS + rq * 4] = v4;
            }
        }
    }

    const int ow = tid >> 3;      // 0..31; outs = ow + 32*ol
    const int tg = tid & 7;       // 0..7;  toks = tg + 8*tl
    float bia[4];
    #pragma unroll
    for (int ol = 0; ol < 4; ol++) bia[ol] = bias[o0 + ow + 32 * ol];

    __syncthreads();

    unsigned long long acc[4][4];   // [ol][tl], r-pair packed partial dots
    #pragma unroll
    for (int i = 0; i < 4; i++)
        #pragma unroll
        for (int j = 0; j < 4; j++) acc[i][j] = 0ull;

    #pragma unroll 4
    for (int rb = 0; rb < 16; rb++) {
        ulonglong2 w2[4], v2[4];
        #pragma unroll
        for (int ol = 0; ol < 4; ol++)
            w2[ol] = *(const ulonglong2*)&Wsm[(ow + 32 * ol) * WS + rb * 4];
        #pragma unroll
        for (int tl = 0; tl < 4; tl++)
            v2[tl] = *(const ulonglong2*)&Vsm[(tg + 8 * tl) * WS + rb * 4];
        #pragma unroll
        for (int ol = 0; ol < 4; ol++)
            #pragma unroll
            for (int tl = 0; tl < 4; tl++) {
                fma2(acc[ol][tl], w2[ol].x, v2[tl].x);
                fma2(acc[ol][tl], w2[ol].y, v2[tl].y);
            }
    }

    #pragma unroll
    for (int tl = 0; tl < 4; tl++) {
        int t = tg + 8 * tl;
        if (t < nt) {
            int tok = g_order[start + t];
            #pragma unroll
            for (int ol = 0; ol < 4; ol++) {
                float lo, hi;
                unpack2(acc[ol][tl], lo, hi);
                out[(size_t)tok * O_DIM + o0 + ow + 32 * ol] = lo + hi + bia[ol];
            }
        }
    }
}

// ---------------- launch ----------------
extern "C" void kernel_launch(void* const* d_in, const int* in_sizes, int n_in,
                              void* d_out, int out_size) {
    const float* x      = (const float*)d_in[0];
    // d_in[1] = key, unused by the forward pass
    const float* map_w  = (const float*)d_in[2];
    const float* map_b  = (const float*)d_in[3];
    const float* pw_w1  = (const float*)d_in[4];
    const float* w21    = (const float*)d_in[5];
    const float* w22    = (const float*)d_in[6];
    const float* pw_B   = (const float*)d_in[7];
    float* out = (float*)d_out;

    k_front<<<N_TOK / 64, 768>>>(x, map_w, map_b, pw_w1);
    k_mid<<<1, 256>>>(out, out_size);
    k_scatter<<<N_TOK / 128, 128>>>();
    k_main<<<dim3(512, O_DIM / 128), 256>>>(w21, w22, pw_B, out);
}